// round 3
// baseline (speedup 1.0000x reference)
#include <cuda_runtime.h>
#include <cuda_bf16.h>
#include <math_constants.h>

#define Q_LEN 2048
#define HIST  2048
#define KLEN  4096
#define NH    12
#define KVH   2
#define DH    128
#define HID   1536
#define KVDIM 256
#define GROUPS 6

// Scratch (device globals: allocation-free)
__device__ float g_q[Q_LEN * HID];      // Q after proj+rope, [t][h*128+d]
__device__ float g_k[KLEN * KVDIM];     // full K (hist + new, rope'd), [t][kvh*128+d]
__device__ float g_v[KLEN * KVDIM];
__device__ float g_att[Q_LEN * HID];    // attention output before Wo

// ---------------------------------------------------------------------------
// Tiled SGEMM body: C[row0.., col0..] (+bias) = A[M,K] @ B[K,N], 128x128 tile,
// BK=16, 256 threads, 8x8 per thread.
// ---------------------------------------------------------------------------
__device__ __forceinline__ void gemm_body(
    const float* __restrict__ A, const float* __restrict__ B,
    const float* __restrict__ bias, float* __restrict__ C,
    int row0, int col0, int N, int K, int ldc)
{
    __shared__ float As[16][128];   // transposed: As[k][m]
    __shared__ float Bs[16][128];   // Bs[k][n]
    const int tid = threadIdx.x;
    const int tx  = tid & 15;
    const int ty  = tid >> 4;

    float acc[8][8];
#pragma unroll
    for (int i = 0; i < 8; i++)
#pragma unroll
        for (int j = 0; j < 8; j++) acc[i][j] = 0.f;

    for (int k0 = 0; k0 < K; k0 += 16) {
#pragma unroll
        for (int l = 0; l < 2; l++) {
            int li = tid + l * 256;
            int r  = li >> 2;            // 0..127 (M within tile)
            int c  = (li & 3) << 2;      // 0,4,8,12 (K within tile)
            float4 v = *(const float4*)(A + (size_t)(row0 + r) * K + (k0 + c));
            As[c + 0][r] = v.x; As[c + 1][r] = v.y;
            As[c + 2][r] = v.z; As[c + 3][r] = v.w;
        }
#pragma unroll
        for (int l = 0; l < 2; l++) {
            int li = tid + l * 256;
            int r  = li >> 5;            // 0..15 (K within tile)
            int c  = (li & 31) << 2;     // 0..124 (N within tile)
            *(float4*)(&Bs[r][c]) =
                *(const float4*)(B + (size_t)(k0 + r) * N + col0 + c);
        }
        __syncthreads();
#pragma unroll
        for (int kk = 0; kk < 16; kk++) {
            float a[8], b[8];
            *(float4*)(a)     = *(const float4*)(&As[kk][ty * 8]);
            *(float4*)(a + 4) = *(const float4*)(&As[kk][ty * 8 + 4]);
            *(float4*)(b)     = *(const float4*)(&Bs[kk][tx * 8]);
            *(float4*)(b + 4) = *(const float4*)(&Bs[kk][tx * 8 + 4]);
#pragma unroll
            for (int i = 0; i < 8; i++)
#pragma unroll
                for (int j = 0; j < 8; j++)
                    acc[i][j] = fmaf(a[i], b[j], acc[i][j]);
        }
        __syncthreads();
    }

    float bb[8];
#pragma unroll
    for (int j = 0; j < 8; j++) bb[j] = bias ? bias[col0 + tx * 8 + j] : 0.f;

#pragma unroll
    for (int i = 0; i < 8; i++) {
        float4 o0, o1;
        o0.x = acc[i][0] + bb[0]; o0.y = acc[i][1] + bb[1];
        o0.z = acc[i][2] + bb[2]; o0.w = acc[i][3] + bb[3];
        o1.x = acc[i][4] + bb[4]; o1.y = acc[i][5] + bb[5];
        o1.z = acc[i][6] + bb[6]; o1.w = acc[i][7] + bb[7];
        float* cp = C + (size_t)(row0 + ty * 8 + i) * ldc + col0 + tx * 8;
        *(float4*)(cp)     = o0;
        *(float4*)(cp + 4) = o1;
    }
}

// Fused QKV projection: grid.x tiles 0..11 -> Wq, 12..13 -> Wk, 14..15 -> Wv
__global__ __launch_bounds__(256) void gemm_qkv_kernel(
    const float* __restrict__ x,
    const float* __restrict__ Wq, const float* __restrict__ bq,
    const float* __restrict__ Wk, const float* __restrict__ bk,
    const float* __restrict__ Wv, const float* __restrict__ bv)
{
    int bx   = blockIdx.x;
    int row0 = blockIdx.y * 128;
    if (bx < 12) {
        gemm_body(x, Wq, bq, g_q, row0, bx * 128, HID, HID, HID);
    } else if (bx < 14) {
        gemm_body(x, Wk, bk, g_k + (size_t)HIST * KVDIM, row0, (bx - 12) * 128,
                  KVDIM, HID, KVDIM);
    } else {
        gemm_body(x, Wv, bv, g_v + (size_t)HIST * KVDIM, row0, (bx - 14) * 128,
                  KVDIM, HID, KVDIM);
    }
}

__global__ __launch_bounds__(256) void gemm_wo_kernel(
    const float* __restrict__ Wo, float* __restrict__ out)
{
    gemm_body(g_att, Wo, nullptr, out, blockIdx.y * 128, blockIdx.x * 128,
              HID, HID, HID);
}

// ---------------------------------------------------------------------------
// RoPE: in-place on Q (12 heads) and new K rows (2 kv heads)
// block = (t * 14 + hh), 64 threads (one per dim pair)
// ---------------------------------------------------------------------------
__global__ __launch_bounds__(64) void rope_kernel(
    const float* __restrict__ fcos, const float* __restrict__ fsin)
{
    int b  = blockIdx.x;
    int t  = b / 14;
    int hh = b % 14;
    int d  = threadIdx.x;   // 0..63
    float c = fcos[t * 64 + d];
    float s = fsin[t * 64 + d];
    float* base;
    if (hh < 12) base = g_q + (size_t)t * HID + hh * DH;
    else         base = g_k + (size_t)(HIST + t) * KVDIM + (hh - 12) * DH;
    float x1 = base[d];
    float x2 = base[d + 64];
    base[d]      = x1 * c - x2 * s;
    base[d + 64] = x1 * s + x2 * c;
}

// ---------------------------------------------------------------------------
// Flash attention: block = (head, 128 q-rows), 64-key tiles, fp32.
// smem: Qs[128][128], Ks[128][68] (d-major), Vs[64][132], Ss[128][68],
//       corr[128], l[128]
// ---------------------------------------------------------------------------
#define ATTN_SMEM_FLOATS (128*128 + 128*68 + 64*132 + 128*68 + 128 + 128)
#define ATTN_SMEM_BYTES  (ATTN_SMEM_FLOATS * 4)

__global__ __launch_bounds__(256) void attn_kernel()
{
    extern __shared__ float sm[];
    float* Qs     = sm;                    // [128][128]
    float* Ks     = Qs + 128 * 128;        // [d][col], stride 68
    float* Vs     = Ks + 128 * 68;         // [row][d], stride 132
    float* Ss     = Vs + 64 * 132;         // [qrow][kcol], stride 68
    float* corr_s = Ss + 128 * 68;
    float* l_s    = corr_s + 128;

    const int head = blockIdx.x;
    const int q0   = blockIdx.y * 128;
    const int kvh  = head / GROUPS;
    const int tid  = threadIdx.x;
    const int tx   = tid & 15;
    const int ty   = tid >> 4;

    // Q tile
    for (int i = tid; i < 128 * 32; i += 256) {
        int r = i >> 5;
        int c = (i & 31) << 2;
        *(float4*)(Qs + r * 128 + c) =
            *(const float4*)(g_q + (size_t)(q0 + r) * HID + head * DH + c);
    }

    float o[8][8];
#pragma unroll
    for (int i = 0; i < 8; i++)
#pragma unroll
        for (int j = 0; j < 8; j++) o[i][j] = 0.f;

    float m_i = -CUDART_INF_F;
    float l_i = 0.f;

    const int nkt = (q0 + 127 + HIST) / 64 + 1;
    for (int kt = 0; kt < nkt; kt++) {
        const int kb = kt * 64;
        // K (transposed into d-major) and V tiles
        for (int i = tid; i < 64 * 32; i += 256) {
            int r = i >> 5;            // key row within tile
            int c = (i & 31) << 2;     // d
            const float* kp = g_k + (size_t)(kb + r) * KVDIM + kvh * DH + c;
            float4 kv = *(const float4*)kp;
            Ks[(c + 0) * 68 + r] = kv.x;
            Ks[(c + 1) * 68 + r] = kv.y;
            Ks[(c + 2) * 68 + r] = kv.z;
            Ks[(c + 3) * 68 + r] = kv.w;
            *(float4*)(Vs + r * 132 + c) =
                *(const float4*)(g_v + (size_t)(kb + r) * KVDIM + kvh * DH + c);
        }
        __syncthreads();

        // S = Q K^T : per-thread 8 rows x 4 cols
        float acc[8][4];
#pragma unroll
        for (int i = 0; i < 8; i++)
#pragma unroll
            for (int j = 0; j < 4; j++) acc[i][j] = 0.f;

        for (int d = 0; d < 128; d += 4) {
            float kreg[4][4];   // kreg[dd][j], j = col within thread's 4
            *(float4*)kreg[0] = *(const float4*)(Ks + (d + 0) * 68 + tx * 4);
            *(float4*)kreg[1] = *(const float4*)(Ks + (d + 1) * 68 + tx * 4);
            *(float4*)kreg[2] = *(const float4*)(Ks + (d + 2) * 68 + tx * 4);
            *(float4*)kreg[3] = *(const float4*)(Ks + (d + 3) * 68 + tx * 4);
#pragma unroll
            for (int i = 0; i < 8; i++) {
                float qreg[4];
                *(float4*)qreg = *(const float4*)(Qs + (ty * 8 + i) * 128 + d);
#pragma unroll
                for (int dd = 0; dd < 4; dd++)
#pragma unroll
                    for (int j = 0; j < 4; j++)
                        acc[i][j] = fmaf(qreg[dd], kreg[dd][j], acc[i][j]);
            }
        }

        const float scale = 0.08838834764831845f;  // 1/sqrt(128)
#pragma unroll
        for (int i = 0; i < 8; i++) {
            int qg = q0 + ty * 8 + i;
#pragma unroll
            for (int j = 0; j < 4; j++) {
                int cg = kb + tx * 4 + j;
                float s = acc[i][j] * scale;
                if (cg > qg + HIST) s = -1e30f;
                Ss[(ty * 8 + i) * 68 + tx * 4 + j] = s;
            }
        }
        __syncthreads();

        // online softmax: thread tid<128 owns row tid
        if (tid < 128) {
            float* srow = Ss + tid * 68;
            float mx = m_i;
            for (int c = 0; c < 64; c++) mx = fmaxf(mx, srow[c]);
            float corr = __expf(m_i - mx);
            float sum = 0.f;
            for (int c = 0; c < 64; c++) {
                float p = __expf(srow[c] - mx);
                srow[c] = p;
                sum += p;
            }
            l_i = l_i * corr + sum;
            m_i = mx;
            corr_s[tid] = corr;
        }
        __syncthreads();

        // rescale O and accumulate P @ V : per-thread 8 rows x 8 cols
        float crr[8];
#pragma unroll
        for (int i = 0; i < 8; i++) crr[i] = corr_s[ty * 8 + i];
#pragma unroll
        for (int i = 0; i < 8; i++)
#pragma unroll
            for (int j = 0; j < 8; j++) o[i][j] *= crr[i];

        for (int kk = 0; kk < 64; kk++) {
            float4 v0 = *(const float4*)(Vs + kk * 132 + tx * 8);
            float4 v1 = *(const float4*)(Vs + kk * 132 + tx * 8 + 4);
#pragma unroll
            for (int i = 0; i < 8; i++) {
                float p = Ss[(ty * 8 + i) * 68 + kk];
                o[i][0] = fmaf(p, v0.x, o[i][0]);
                o[i][1] = fmaf(p, v0.y, o[i][1]);
                o[i][2] = fmaf(p, v0.z, o[i][2]);
                o[i][3] = fmaf(p, v0.w, o[i][3]);
                o[i][4] = fmaf(p, v1.x, o[i][4]);
                o[i][5] = fmaf(p, v1.y, o[i][5]);
                o[i][6] = fmaf(p, v1.z, o[i][6]);
                o[i][7] = fmaf(p, v1.w, o[i][7]);
            }
        }
        __syncthreads();
    }

    if (tid < 128) l_s[tid] = l_i;
    __syncthreads();

#pragma unroll
    for (int i = 0; i < 8; i++) {
        float inv = 1.f / l_s[ty * 8 + i];
        float4 o0 = make_float4(o[i][0] * inv, o[i][1] * inv,
                                o[i][2] * inv, o[i][3] * inv);
        float4 o1 = make_float4(o[i][4] * inv, o[i][5] * inv,
                                o[i][6] * inv, o[i][7] * inv);
        float* ap = g_att + (size_t)(q0 + ty * 8 + i) * HID + head * DH + tx * 8;
        *(float4*)(ap)     = o0;
        *(float4*)(ap + 4) = o1;
    }
}

// ---------------------------------------------------------------------------
extern "C" void kernel_launch(void* const* d_in, const int* in_sizes, int n_in,
                              void* d_out, int out_size)
{
    const float* x      = (const float*)d_in[0];
    const float* Wq     = (const float*)d_in[1];
    const float* bq     = (const float*)d_in[2];
    const float* Wk     = (const float*)d_in[3];
    const float* bk     = (const float*)d_in[4];
    const float* Wv     = (const float*)d_in[5];
    const float* bv     = (const float*)d_in[6];
    const float* Wo     = (const float*)d_in[7];
    const float* k_hist = (const float*)d_in[8];
    const float* v_hist = (const float*)d_in[9];
    const float* fcos   = (const float*)d_in[10];
    const float* fsin   = (const float*)d_in[11];
    float* out = (float*)d_out;

    // Non-stream host APIs first (safe under capture, but keep them ahead of
    // any enqueued work).
    cudaFuncSetAttribute(attn_kernel,
                         cudaFuncAttributeMaxDynamicSharedMemorySize,
                         ATTN_SMEM_BYTES);
    float *kp = nullptr, *vp = nullptr;
    cudaGetSymbolAddress((void**)&kp, g_k);
    cudaGetSymbolAddress((void**)&vp, g_v);

    // history prefix of K/V
    cudaMemcpyAsync(kp, k_hist, (size_t)HIST * KVDIM * sizeof(float),
                    cudaMemcpyDeviceToDevice, 0);
    cudaMemcpyAsync(vp, v_hist, (size_t)HIST * KVDIM * sizeof(float),
                    cudaMemcpyDeviceToDevice, 0);

    // fused QKV projection
    gemm_qkv_kernel<<<dim3(16, 16), 256>>>(x, Wq, bq, Wk, bk, Wv, bv);

    // RoPE on Q and new K rows
    rope_kernel<<<Q_LEN * 14, 64>>>(fcos, fsin);

    // attention
    attn_kernel<<<dim3(NH, Q_LEN / 128), 256, ATTN_SMEM_BYTES>>>();

    // output projection
    gemm_wo_kernel<<<dim3(HID / 128, Q_LEN / 128), 256>>>(Wo, out);
}

// round 4
// speedup vs baseline: 3.8231x; 3.8231x over previous
#include <cuda_runtime.h>
#include <cuda_bf16.h>
#include <math_constants.h>
#include <cstdint>

#define Q_LEN 2048
#define HIST  2048
#define KLEN  4096
#define NH    12
#define KVH   2
#define DH    128
#define HID   1536
#define KVDIM 256
#define GROUPS 6

// Scratch (device globals: allocation-free)
__device__ float g_q[Q_LEN * HID];      // Q after proj+rope
__device__ float g_k[KLEN * KVDIM];     // full K (hist + new, rope'd)
__device__ float g_v[KLEN * KVDIM];
__device__ float g_att[Q_LEN * HID];    // attention output before Wo

// ---------------------------------------------------------------------------
// tf32 helpers
// ---------------------------------------------------------------------------
__device__ __forceinline__ float tf32r(float x) {
    uint32_t u;
    asm("cvt.rna.tf32.f32 %0, %1;" : "=r"(u) : "f"(x));
    return __uint_as_float(u);
}
__device__ __forceinline__ uint32_t fbits(float x) { return __float_as_uint(x); }

__device__ __forceinline__ void mma_tf32(float d[4], const uint32_t a[4],
                                         const uint32_t b[2]) {
    asm volatile(
        "mma.sync.aligned.m16n8k8.row.col.f32.tf32.tf32.f32 "
        "{%0,%1,%2,%3}, {%4,%5,%6,%7}, {%8,%9}, {%0,%1,%2,%3};\n"
        : "+f"(d[0]), "+f"(d[1]), "+f"(d[2]), "+f"(d[3])
        : "r"(a[0]), "r"(a[1]), "r"(a[2]), "r"(a[3]), "r"(b[0]), "r"(b[1]));
}

// ---------------------------------------------------------------------------
// tf32 tensor-core GEMM body: C[row0..+128, col0..+128] = A[M,K]@B[K,N] (+bias)
// 256 threads = 8 warps in 2(M) x 4(N); warp tile 64x32; BK=32.
// ---------------------------------------------------------------------------
#define LDA_G 36
#define LDB_G 136

__device__ __forceinline__ void gemm_body_mma(
    const float* __restrict__ A, const float* __restrict__ B,
    const float* __restrict__ bias, float* __restrict__ C,
    int row0, int col0, int N, int K, int ldc)
{
    __shared__ float As[128 * LDA_G];   // [m][k]
    __shared__ float Bs[32 * LDB_G];    // [k][n]

    const int tid  = threadIdx.x;
    const int w    = tid >> 5;
    const int lane = tid & 31;
    const int g    = lane >> 2;
    const int t    = lane & 3;
    const int wm   = w >> 2;    // 0..1
    const int wn   = w & 3;     // 0..3

    float acc[16][4];
#pragma unroll
    for (int i = 0; i < 16; i++)
#pragma unroll
        for (int j = 0; j < 4; j++) acc[i][j] = 0.f;

    for (int k0 = 0; k0 < K; k0 += 32) {
        // A tile 128x32 (tf32-rounded)
#pragma unroll
        for (int l = 0; l < 4; l++) {
            int i = tid + l * 256;          // float4 index, 1024 total
            int r = i >> 3, c = (i & 7) << 2;
            float4 v = *(const float4*)(A + (size_t)(row0 + r) * K + k0 + c);
            float* d = As + r * LDA_G + c;
            d[0] = tf32r(v.x); d[1] = tf32r(v.y);
            d[2] = tf32r(v.z); d[3] = tf32r(v.w);
        }
        // B tile 32x128
#pragma unroll
        for (int l = 0; l < 4; l++) {
            int i = tid + l * 256;
            int r = i >> 5, c = (i & 31) << 2;
            float4 v = *(const float4*)(B + (size_t)(k0 + r) * N + col0 + c);
            float* d = Bs + r * LDB_G + c;
            d[0] = tf32r(v.x); d[1] = tf32r(v.y);
            d[2] = tf32r(v.z); d[3] = tf32r(v.w);
        }
        __syncthreads();

#pragma unroll
        for (int k8 = 0; k8 < 32; k8 += 8) {
            uint32_t a[4][4];
#pragma unroll
            for (int mi = 0; mi < 4; mi++) {
                const float* ab = As + (wm * 64 + mi * 16 + g) * LDA_G + k8 + t;
                a[mi][0] = fbits(ab[0]);
                a[mi][1] = fbits(ab[8 * LDA_G]);
                a[mi][2] = fbits(ab[4]);
                a[mi][3] = fbits(ab[8 * LDA_G + 4]);
            }
#pragma unroll
            for (int ni = 0; ni < 4; ni++) {
                uint32_t b[2];
                const float* bp = Bs + (k8 + t) * LDB_G + wn * 32 + ni * 8 + g;
                b[0] = fbits(bp[0]);
                b[1] = fbits(bp[4 * LDB_G]);
#pragma unroll
                for (int mi = 0; mi < 4; mi++)
                    mma_tf32(acc[mi * 4 + ni], a[mi], b);
            }
        }
        __syncthreads();
    }

#pragma unroll
    for (int mi = 0; mi < 4; mi++)
#pragma unroll
        for (int ni = 0; ni < 4; ni++) {
            int col = col0 + wn * 32 + ni * 8 + 2 * t;
            float b0 = bias ? bias[col]     : 0.f;
            float b1 = bias ? bias[col + 1] : 0.f;
            int r0 = row0 + wm * 64 + mi * 16 + g;
            float* c0 = C + (size_t)r0 * ldc + col;
            float* c1 = C + (size_t)(r0 + 8) * ldc + col;
            *(float2*)c0 = make_float2(acc[mi * 4 + ni][0] + b0,
                                       acc[mi * 4 + ni][1] + b1);
            *(float2*)c1 = make_float2(acc[mi * 4 + ni][2] + b0,
                                       acc[mi * 4 + ni][3] + b1);
        }
}

// Fused QKV projection: grid.x tiles 0..11 -> Wq, 12..13 -> Wk, 14..15 -> Wv
__global__ __launch_bounds__(256) void gemm_qkv_kernel(
    const float* __restrict__ x,
    const float* __restrict__ Wq, const float* __restrict__ bq,
    const float* __restrict__ Wk, const float* __restrict__ bk,
    const float* __restrict__ Wv, const float* __restrict__ bv)
{
    int bx   = blockIdx.x;
    int row0 = blockIdx.y * 128;
    if (bx < 12) {
        gemm_body_mma(x, Wq, bq, g_q, row0, bx * 128, HID, HID, HID);
    } else if (bx < 14) {
        gemm_body_mma(x, Wk, bk, g_k + (size_t)HIST * KVDIM, row0,
                      (bx - 12) * 128, KVDIM, HID, KVDIM);
    } else {
        gemm_body_mma(x, Wv, bv, g_v + (size_t)HIST * KVDIM, row0,
                      (bx - 14) * 128, KVDIM, HID, KVDIM);
    }
}

__global__ __launch_bounds__(256) void gemm_wo_kernel(
    const float* __restrict__ Wo, float* __restrict__ out)
{
    gemm_body_mma(g_att, Wo, nullptr, out, blockIdx.y * 128,
                  blockIdx.x * 128, HID, HID, HID);
}

// ---------------------------------------------------------------------------
// RoPE: in-place on Q (12 heads) and new K rows (2 kv heads)
// ---------------------------------------------------------------------------
__global__ __launch_bounds__(64) void rope_kernel(
    const float* __restrict__ fcos, const float* __restrict__ fsin)
{
    int b  = blockIdx.x;
    int t  = b / 14;
    int hh = b % 14;
    int d  = threadIdx.x;   // 0..63
    float c = fcos[t * 64 + d];
    float s = fsin[t * 64 + d];
    float* base;
    if (hh < 12) base = g_q + (size_t)t * HID + hh * DH;
    else         base = g_k + (size_t)(HIST + t) * KVDIM + (hh - 12) * DH;
    float x1 = base[d];
    float x2 = base[d + 64];
    base[d]      = x1 * c - x2 * s;
    base[d + 64] = x1 * s + x2 * c;
}

// ---------------------------------------------------------------------------
// Flash attention, tf32 mma: CTA = (head, 128 q-rows), 64-key tiles.
// 8 warps; warp w owns q-rows [w*16, w*16+16) end-to-end (S, softmax, O).
// ---------------------------------------------------------------------------
#define LDQ 132
#define LDK 132
#define LDV 136
#define LDP 68
#define ATTN_SMEM_FLOATS (128*LDQ + 64*LDK + 64*LDV + 128*LDP)
#define ATTN_SMEM_BYTES  (ATTN_SMEM_FLOATS * 4)

__global__ __launch_bounds__(256) void attn_kernel()
{
    extern __shared__ float sm[];
    float* Qs = sm;                    // [128][LDQ]  (q-row, d)
    float* Ks = Qs + 128 * LDQ;        // [64][LDK]   (key, d)
    float* Vs = Ks + 64 * LDK;         // [64][LDV]   (key, d)
    float* Ps = Vs + 64 * LDV;         // [128][LDP]  (q-row, key) per-warp slabs

    const int bid  = blockIdx.x;
    const int qt   = 15 - bid / NH;        // descending q-tile (load balance)
    const int head = bid % NH;
    const int q0   = qt * 128;
    const int kvh  = head / GROUPS;
    const int tid  = threadIdx.x;
    const int w    = tid >> 5;
    const int lane = tid & 31;
    const int g    = lane >> 2;
    const int t    = lane & 3;

    // Q tile (tf32-rounded)
#pragma unroll
    for (int l = 0; l < 16; l++) {
        int i = tid + l * 256;           // float4 index, 4096 total
        int r = i >> 5, c = (i & 31) << 2;
        float4 v = *(const float4*)(g_q + (size_t)(q0 + r) * HID + head * DH + c);
        float* d = Qs + r * LDQ + c;
        d[0] = tf32r(v.x); d[1] = tf32r(v.y);
        d[2] = tf32r(v.z); d[3] = tf32r(v.w);
    }

    float o[16][4];
#pragma unroll
    for (int i = 0; i < 16; i++)
#pragma unroll
        for (int j = 0; j < 4; j++) o[i][j] = 0.f;

    float m0 = -1e30f, m1 = -1e30f, l0 = 0.f, l1 = 0.f;
    const int row0g = q0 + w * 16 + g;      // global q row of register row 0
    const float SC = 0.12751689932560563f;  // 1/sqrt(128) * log2(e)

    const int nkt = (q0 + 128 + HIST) / 64;
    for (int kt = 0; kt < nkt; kt++) {
        const int kb = kt * 64;
        // K, V tiles (tf32-rounded)
#pragma unroll
        for (int l = 0; l < 8; l++) {
            int i = tid + l * 256;
            int r = i >> 5, c = (i & 31) << 2;
            const float* src = g_k + (size_t)(kb + r) * KVDIM + kvh * DH + c;
            float4 kv = *(const float4*)src;
            float4 vv = *(const float4*)(src + (g_v - g_k));
            float* kd = Ks + r * LDK + c;
            kd[0] = tf32r(kv.x); kd[1] = tf32r(kv.y);
            kd[2] = tf32r(kv.z); kd[3] = tf32r(kv.w);
            float* vd = Vs + r * LDV + c;
            vd[0] = tf32r(vv.x); vd[1] = tf32r(vv.y);
            vd[2] = tf32r(vv.z); vd[3] = tf32r(vv.w);
        }
        __syncthreads();

        // S = Q K^T : warp rows 16 x 64 keys
        float s[8][4];
#pragma unroll
        for (int j = 0; j < 8; j++)
#pragma unroll
            for (int e = 0; e < 4; e++) s[j][e] = 0.f;

#pragma unroll
        for (int k8 = 0; k8 < 128; k8 += 8) {
            uint32_t a[4];
            const float* qb = Qs + (w * 16 + g) * LDQ + k8 + t;
            a[0] = fbits(qb[0]);
            a[1] = fbits(qb[8 * LDQ]);
            a[2] = fbits(qb[4]);
            a[3] = fbits(qb[8 * LDQ + 4]);
#pragma unroll
            for (int j = 0; j < 8; j++) {
                uint32_t b[2];
                const float* kp = Ks + (j * 8 + g) * LDK + k8 + t;
                b[0] = fbits(kp[0]);
                b[1] = fbits(kp[4]);
                mma_tf32(s[j], a, b);
            }
        }

        // scale (into log2 domain) + causal mask
#pragma unroll
        for (int j = 0; j < 8; j++) {
            int colg = kb + j * 8 + 2 * t;
            s[j][0] = (colg     <= row0g + HIST)     ? s[j][0] * SC : -1e30f;
            s[j][1] = (colg + 1 <= row0g + HIST)     ? s[j][1] * SC : -1e30f;
            s[j][2] = (colg     <= row0g + 8 + HIST) ? s[j][2] * SC : -1e30f;
            s[j][3] = (colg + 1 <= row0g + 8 + HIST) ? s[j][3] * SC : -1e30f;
        }

        // row max (quad reduce)
        float mx0 = -1e30f, mx1 = -1e30f;
#pragma unroll
        for (int j = 0; j < 8; j++) {
            mx0 = fmaxf(mx0, fmaxf(s[j][0], s[j][1]));
            mx1 = fmaxf(mx1, fmaxf(s[j][2], s[j][3]));
        }
        mx0 = fmaxf(mx0, __shfl_xor_sync(0xffffffffu, mx0, 1));
        mx0 = fmaxf(mx0, __shfl_xor_sync(0xffffffffu, mx0, 2));
        mx1 = fmaxf(mx1, __shfl_xor_sync(0xffffffffu, mx1, 1));
        mx1 = fmaxf(mx1, __shfl_xor_sync(0xffffffffu, mx1, 2));

        float mn0 = fmaxf(m0, mx0), mn1 = fmaxf(m1, mx1);
        float c0 = exp2f(m0 - mn0), c1 = exp2f(m1 - mn1);
        m0 = mn0; m1 = mn1;

        float sum0 = 0.f, sum1 = 0.f;
#pragma unroll
        for (int j = 0; j < 8; j++) {
            s[j][0] = exp2f(s[j][0] - m0);
            s[j][1] = exp2f(s[j][1] - m0);
            s[j][2] = exp2f(s[j][2] - m1);
            s[j][3] = exp2f(s[j][3] - m1);
            sum0 += s[j][0] + s[j][1];
            sum1 += s[j][2] + s[j][3];
        }
        sum0 += __shfl_xor_sync(0xffffffffu, sum0, 1);
        sum0 += __shfl_xor_sync(0xffffffffu, sum0, 2);
        sum1 += __shfl_xor_sync(0xffffffffu, sum1, 1);
        sum1 += __shfl_xor_sync(0xffffffffu, sum1, 2);
        l0 = l0 * c0 + sum0;
        l1 = l1 * c1 + sum1;

        // rescale O
#pragma unroll
        for (int j = 0; j < 16; j++) {
            o[j][0] *= c0; o[j][1] *= c0;
            o[j][2] *= c1; o[j][3] *= c1;
        }

        // stage P (tf32) in this warp's private slab
        {
            float* p0 = Ps + (w * 16 + g) * LDP;
            float* p1 = p0 + 8 * LDP;
#pragma unroll
            for (int j = 0; j < 8; j++) {
                *(float2*)(p0 + j * 8 + 2 * t) =
                    make_float2(tf32r(s[j][0]), tf32r(s[j][1]));
                *(float2*)(p1 + j * 8 + 2 * t) =
                    make_float2(tf32r(s[j][2]), tf32r(s[j][3]));
            }
        }
        __syncwarp();

        // O += P @ V : 16 x 128 per warp
#pragma unroll
        for (int k8 = 0; k8 < 64; k8 += 8) {
            uint32_t a[4];
            const float* pb = Ps + (w * 16 + g) * LDP + k8 + t;
            a[0] = fbits(pb[0]);
            a[1] = fbits(pb[8 * LDP]);
            a[2] = fbits(pb[4]);
            a[3] = fbits(pb[8 * LDP + 4]);
#pragma unroll
            for (int j = 0; j < 16; j++) {
                uint32_t b[2];
                const float* vb = Vs + (k8 + t) * LDV + j * 8 + g;
                b[0] = fbits(vb[0]);
                b[1] = fbits(vb[4 * LDV]);
                mma_tf32(o[j], a, b);
            }
        }
        __syncthreads();
    }

    // normalize + store
    float inv0 = 1.f / l0, inv1 = 1.f / l1;
#pragma unroll
    for (int j = 0; j < 16; j++) {
        float* a0 = g_att + (size_t)(row0g)     * HID + head * DH + j * 8 + 2 * t;
        float* a1 = g_att + (size_t)(row0g + 8) * HID + head * DH + j * 8 + 2 * t;
        *(float2*)a0 = make_float2(o[j][0] * inv0, o[j][1] * inv0);
        *(float2*)a1 = make_float2(o[j][2] * inv1, o[j][3] * inv1);
    }
}

// ---------------------------------------------------------------------------
extern "C" void kernel_launch(void* const* d_in, const int* in_sizes, int n_in,
                              void* d_out, int out_size)
{
    const float* x      = (const float*)d_in[0];
    const float* Wq     = (const float*)d_in[1];
    const float* bq     = (const float*)d_in[2];
    const float* Wk     = (const float*)d_in[3];
    const float* bk     = (const float*)d_in[4];
    const float* Wv     = (const float*)d_in[5];
    const float* bv     = (const float*)d_in[6];
    const float* Wo     = (const float*)d_in[7];
    const float* k_hist = (const float*)d_in[8];
    const float* v_hist = (const float*)d_in[9];
    const float* fcos   = (const float*)d_in[10];
    const float* fsin   = (const float*)d_in[11];
    float* out = (float*)d_out;

    cudaFuncSetAttribute(attn_kernel,
                         cudaFuncAttributeMaxDynamicSharedMemorySize,
                         ATTN_SMEM_BYTES);
    float *kp = nullptr, *vp = nullptr;
    cudaGetSymbolAddress((void**)&kp, g_k);
    cudaGetSymbolAddress((void**)&vp, g_v);

    // history prefix of K/V
    cudaMemcpyAsync(kp, k_hist, (size_t)HIST * KVDIM * sizeof(float),
                    cudaMemcpyDeviceToDevice, 0);
    cudaMemcpyAsync(vp, v_hist, (size_t)HIST * KVDIM * sizeof(float),
                    cudaMemcpyDeviceToDevice, 0);

    // fused QKV projection (tensor core tf32)
    gemm_qkv_kernel<<<dim3(16, 16), 256>>>(x, Wq, bq, Wk, bk, Wv, bv);

    // RoPE on Q and new K rows
    rope_kernel<<<Q_LEN * 14, 64>>>(fcos, fsin);

    // attention (tensor core tf32)
    attn_kernel<<<NH * (Q_LEN / 128), 256, ATTN_SMEM_BYTES>>>();

    // output projection
    gemm_wo_kernel<<<dim3(HID / 128, Q_LEN / 128), 256>>>(Wo, out);
}

// round 6
// speedup vs baseline: 4.5155x; 1.1811x over previous
#include <cuda_runtime.h>
#include <cuda_bf16.h>
#include <math_constants.h>
#include <cstdint>

#define Q_LEN 2048
#define HIST  2048
#define KLEN  4096
#define NH    12
#define KVH   2
#define DH    128
#define HID   1536
#define KVDIM 256
#define GROUPS 6
#define NITEMS (NH * 16)

// Scratch (device globals: allocation-free)
__device__ __align__(16) float g_q[Q_LEN * HID];
__device__ __align__(16) float g_k[KLEN * KVDIM];
__device__ __align__(16) float g_v[KLEN * KVDIM];
__device__ __align__(16) float g_att[Q_LEN * HID];
// tf32-pre-rounded copies of inputs
__device__ __align__(16) float g_x[Q_LEN * HID];
__device__ __align__(16) float g_wq[HID * HID];
__device__ __align__(16) float g_wk[HID * KVDIM];
__device__ __align__(16) float g_wv[HID * KVDIM];
__device__ __align__(16) float g_wo[HID * HID];
__device__ unsigned int g_work;

// ---------------------------------------------------------------------------
// helpers
// ---------------------------------------------------------------------------
__device__ __forceinline__ float tf32r(float x) {
    uint32_t u;
    asm("cvt.rna.tf32.f32 %0, %1;" : "=r"(u) : "f"(x));
    return __uint_as_float(u);
}
__device__ __forceinline__ uint32_t fbits(float x) { return __float_as_uint(x); }

__device__ __forceinline__ void mma_tf32(float d[4], const uint32_t a[4],
                                         const uint32_t b[2]) {
    asm volatile(
        "mma.sync.aligned.m16n8k8.row.col.f32.tf32.tf32.f32 "
        "{%0,%1,%2,%3}, {%4,%5,%6,%7}, {%8,%9}, {%0,%1,%2,%3};\n"
        : "+f"(d[0]), "+f"(d[1]), "+f"(d[2]), "+f"(d[3])
        : "r"(a[0]), "r"(a[1]), "r"(a[2]), "r"(a[3]), "r"(b[0]), "r"(b[1]));
}

__device__ __forceinline__ void cpa16(float* dst, const float* src) {
    uint32_t d = (uint32_t)__cvta_generic_to_shared(dst);
    asm volatile("cp.async.cg.shared.global [%0], [%1], 16;\n"
                 :: "r"(d), "l"(src));
}
#define CP_COMMIT() asm volatile("cp.async.commit_group;\n")
#define CP_WAIT(n)  asm volatile("cp.async.wait_group %0;\n" :: "n"(n))

// ---------------------------------------------------------------------------
// Convert inputs to tf32-rounded copies; reset work counter; fill K/V history.
// ---------------------------------------------------------------------------
__global__ __launch_bounds__(256) void cvt_kernel(
    const float4* __restrict__ x,  const float4* __restrict__ wq,
    const float4* __restrict__ wk, const float4* __restrict__ wv,
    const float4* __restrict__ wo, const float4* __restrict__ kh,
    const float4* __restrict__ vh)
{
    if (blockIdx.x == 0 && threadIdx.x == 0) g_work = 0u;
    const int NX = Q_LEN * HID / 4, NWQ = HID * HID / 4;
    const int NWK = HID * KVDIM / 4, NWV = NWK, NWO = NWQ;
    const int NKH = HIST * KVDIM / 4, NVH = NKH;
    const int total = NX + NWQ + NWK + NWV + NWO + NKH + NVH;
    int stride = gridDim.x * blockDim.x;
    for (int i = blockIdx.x * blockDim.x + threadIdx.x; i < total; i += stride) {
        const float4* src; float4* dst; int j = i;
        if (j < NX)            { src = x;  dst = (float4*)g_x; }
        else if ((j -= NX)  < NWQ) { src = wq; dst = (float4*)g_wq; }
        else if ((j -= NWQ) < NWK) { src = wk; dst = (float4*)g_wk; }
        else if ((j -= NWK) < NWV) { src = wv; dst = (float4*)g_wv; }
        else if ((j -= NWV) < NWO) { src = wo; dst = (float4*)g_wo; }
        else if ((j -= NWO) < NKH) { src = kh; dst = (float4*)g_k; }
        else { j -= NKH;             src = vh; dst = (float4*)g_v; }
        float4 v = src[j];
        dst[j] = make_float4(tf32r(v.x), tf32r(v.y), tf32r(v.z), tf32r(v.w));
    }
}

// ---------------------------------------------------------------------------
// tf32 GEMM with cp.async 2-stage pipeline.
// C[row0..+128, col0..+128] = A[M,K]@B[K,N] (+bias). 8 warps 2x4, warp 64x32.
// ---------------------------------------------------------------------------
#define LDA_G 36
#define LDB_G 136
#define GEMM_SMEM ((2 * 128 * LDA_G + 2 * 32 * LDB_G) * 4)

__device__ __forceinline__ void gemm_body_cp(
    const float* __restrict__ A, const float* __restrict__ B,
    const float* __restrict__ bias, float* __restrict__ C,
    int row0, int col0, int N, int K, int ldc, bool round_out)
{
    extern __shared__ float smg[];
    float* As = smg;
    float* Bs = smg + 2 * 128 * LDA_G;

    const int tid  = threadIdx.x;
    const int w    = tid >> 5;
    const int lane = tid & 31;
    const int g    = lane >> 2;
    const int t    = lane & 3;
    const int wm   = w >> 2;
    const int wn   = w & 3;

    float acc[16][4];
#pragma unroll
    for (int i = 0; i < 16; i++)
#pragma unroll
        for (int j = 0; j < 4; j++) acc[i][j] = 0.f;

    auto load_stage = [&](int s, int k0) {
#pragma unroll
        for (int l = 0; l < 4; l++) {
            int i = tid + l * 256;
            int r = i >> 3, c = (i & 7) << 2;
            cpa16(As + (s * 128 + r) * LDA_G + c,
                  A + (size_t)(row0 + r) * K + k0 + c);
        }
#pragma unroll
        for (int l = 0; l < 4; l++) {
            int i = tid + l * 256;
            int r = i >> 5, c = (i & 31) << 2;
            cpa16(Bs + (s * 32 + r) * LDB_G + c,
                  B + (size_t)(k0 + r) * N + col0 + c);
        }
        CP_COMMIT();
    };

    load_stage(0, 0);
    const int KT = K / 32;
    for (int kt = 0; kt < KT; kt++) {
        if (kt + 1 < KT) { load_stage((kt + 1) & 1, (kt + 1) * 32); CP_WAIT(1); }
        else             { CP_WAIT(0); }
        __syncthreads();
        const float* Ab = As + (kt & 1) * 128 * LDA_G;
        const float* Bb = Bs + (kt & 1) * 32 * LDB_G;
#pragma unroll
        for (int k8 = 0; k8 < 32; k8 += 8) {
            uint32_t a[4][4];
#pragma unroll
            for (int mi = 0; mi < 4; mi++) {
                const float* ab = Ab + (wm * 64 + mi * 16 + g) * LDA_G + k8 + t;
                a[mi][0] = fbits(ab[0]);
                a[mi][1] = fbits(ab[8 * LDA_G]);
                a[mi][2] = fbits(ab[4]);
                a[mi][3] = fbits(ab[8 * LDA_G + 4]);
            }
#pragma unroll
            for (int ni = 0; ni < 4; ni++) {
                uint32_t b[2];
                const float* bp = Bb + (k8 + t) * LDB_G + wn * 32 + ni * 8 + g;
                b[0] = fbits(bp[0]);
                b[1] = fbits(bp[4 * LDB_G]);
#pragma unroll
                for (int mi = 0; mi < 4; mi++)
                    mma_tf32(acc[mi * 4 + ni], a[mi], b);
            }
        }
        __syncthreads();
    }

#pragma unroll
    for (int mi = 0; mi < 4; mi++)
#pragma unroll
        for (int ni = 0; ni < 4; ni++) {
            int col = col0 + wn * 32 + ni * 8 + 2 * t;
            float b0 = bias ? bias[col]     : 0.f;
            float b1 = bias ? bias[col + 1] : 0.f;
            int r0 = row0 + wm * 64 + mi * 16 + g;
            float v00 = acc[mi * 4 + ni][0] + b0;
            float v01 = acc[mi * 4 + ni][1] + b1;
            float v10 = acc[mi * 4 + ni][2] + b0;
            float v11 = acc[mi * 4 + ni][3] + b1;
            if (round_out) {
                v00 = tf32r(v00); v01 = tf32r(v01);
                v10 = tf32r(v10); v11 = tf32r(v11);
            }
            *(float2*)(C + (size_t)r0 * ldc + col)       = make_float2(v00, v01);
            *(float2*)(C + (size_t)(r0 + 8) * ldc + col) = make_float2(v10, v11);
        }
}

// grid.x: 0..11 -> Wq, 12..13 -> Wk, 14..15 -> Wv
__global__ __launch_bounds__(256) void gemm_qkv_kernel(
    const float* __restrict__ bq, const float* __restrict__ bk,
    const float* __restrict__ bv)
{
    int bx   = blockIdx.x;
    int row0 = blockIdx.y * 128;
    if (bx < 12) {
        gemm_body_cp(g_x, g_wq, bq, g_q, row0, bx * 128, HID, HID, HID, false);
    } else if (bx < 14) {
        gemm_body_cp(g_x, g_wk, bk, g_k + (size_t)HIST * KVDIM, row0,
                     (bx - 12) * 128, KVDIM, HID, KVDIM, true);
    } else {
        gemm_body_cp(g_x, g_wv, bv, g_v + (size_t)HIST * KVDIM, row0,
                     (bx - 14) * 128, KVDIM, HID, KVDIM, true);
    }
}

__global__ __launch_bounds__(256) void gemm_wo_kernel(float* __restrict__ out)
{
    gemm_body_cp(g_att, g_wo, nullptr, out, blockIdx.y * 128,
                 blockIdx.x * 128, HID, HID, HID, false);
}

// ---------------------------------------------------------------------------
// RoPE (writes tf32-rounded)
// ---------------------------------------------------------------------------
__global__ __launch_bounds__(64) void rope_kernel(
    const float* __restrict__ fcos, const float* __restrict__ fsin)
{
    int b  = blockIdx.x;
    int t  = b / 14;
    int hh = b % 14;
    int d  = threadIdx.x;   // 0..63
    float c = fcos[t * 64 + d];
    float s = fsin[t * 64 + d];
    float* base;
    if (hh < 12) base = g_q + (size_t)t * HID + hh * DH;
    else         base = g_k + (size_t)(HIST + t) * KVDIM + (hh - 12) * DH;
    float x1 = base[d];
    float x2 = base[d + 64];
    base[d]      = tf32r(x1 * c - x2 * s);
    base[d + 64] = tf32r(x1 * s + x2 * c);
}

// ---------------------------------------------------------------------------
// Persistent flash attention, tf32 mma, cp.async pipelined.
// K double-buffered; V single-buffered (load overlapped behind S phase).
// ---------------------------------------------------------------------------
#define LDQ 132
#define LDK 132
#define LDV 136
#define LDP 68
#define AK_OFF (128 * LDQ)
#define AV_OFF (AK_OFF + 2 * 64 * LDK)
#define AP_OFF (AV_OFF + 64 * LDV)
#define AW_OFF (AP_OFF + 128 * LDP)
#define ATTN_SMEM ((AW_OFF + 4) * 4)

__global__ __launch_bounds__(256) void attn_kernel()
{
    extern __shared__ float sm[];
    float* Qs = sm;
    float* Ks = sm + AK_OFF;
    float* Vs = sm + AV_OFF;
    float* Ps = sm + AP_OFF;
    int* widx = (int*)(sm + AW_OFF);

    const int tid  = threadIdx.x;
    const int w    = tid >> 5;
    const int lane = tid & 31;
    const int g    = lane >> 2;
    const int t    = lane & 3;
    const float SC = 0.12751689932560563f;  // 1/sqrt(128) * log2(e)

    for (;;) {
        if (tid == 0) *widx = (int)atomicAdd(&g_work, 1u);
        __syncthreads();
        const int item = *widx;
        if (item >= NITEMS) break;
        const int qt   = 15 - item / NH;     // descending nkt (LPT)
        const int head = item % NH;
        const int q0   = qt * 128;
        const int kvh  = head / GROUPS;

        // Q tile (pre-rounded in g_q)
#pragma unroll
        for (int l = 0; l < 16; l++) {
            int i = tid + l * 256;
            int r = i >> 5, c = (i & 31) << 2;
            cpa16(Qs + r * LDQ + c, g_q + (size_t)(q0 + r) * HID + head * DH + c);
        }
        CP_COMMIT();
        // K(0) into stage 0
#pragma unroll
        for (int l = 0; l < 8; l++) {
            int i = tid + l * 256;
            int r = i >> 5, c = (i & 31) << 2;
            cpa16(Ks + r * LDK + c, g_k + (size_t)r * KVDIM + kvh * DH + c);
        }
        CP_COMMIT();

        float o[16][4];
#pragma unroll
        for (int i = 0; i < 16; i++)
#pragma unroll
            for (int j = 0; j < 4; j++) o[i][j] = 0.f;
        float m0 = -1e30f, m1 = -1e30f, l0 = 0.f, l1 = 0.f;
        const int row0g = q0 + w * 16 + g;
        const int nkt = (q0 + 128 + HIST) / 64;

        for (int kt = 0; kt < nkt; kt++) {
            const int kb = kt * 64;
            const float* Kcur = Ks + (kt & 1) * 64 * LDK;
            const bool more = (kt + 1 < nkt);

            // issue V(kt)
#pragma unroll
            for (int l = 0; l < 8; l++) {
                int i = tid + l * 256;
                int r = i >> 5, c = (i & 31) << 2;
                cpa16(Vs + r * LDV + c,
                      g_v + (size_t)(kb + r) * KVDIM + kvh * DH + c);
            }
            CP_COMMIT();
            // issue K(kt+1)
            if (more) {
                float* Knx = Ks + ((kt + 1) & 1) * 64 * LDK;
#pragma unroll
                for (int l = 0; l < 8; l++) {
                    int i = tid + l * 256;
                    int r = i >> 5, c = (i & 31) << 2;
                    cpa16(Knx + r * LDK + c,
                          g_k + (size_t)(kb + 64 + r) * KVDIM + kvh * DH + c);
                }
                CP_COMMIT();
                CP_WAIT(2);          // K(kt) (and Q on first iter) done
            } else {
                CP_WAIT(1);
            }
            __syncthreads();

            // S = Q K^T
            float s[8][4];
#pragma unroll
            for (int j = 0; j < 8; j++)
#pragma unroll
                for (int e = 0; e < 4; e++) s[j][e] = 0.f;
#pragma unroll
            for (int k8 = 0; k8 < 128; k8 += 8) {
                uint32_t a[4];
                const float* qb = Qs + (w * 16 + g) * LDQ + k8 + t;
                a[0] = fbits(qb[0]);
                a[1] = fbits(qb[8 * LDQ]);
                a[2] = fbits(qb[4]);
                a[3] = fbits(qb[8 * LDQ + 4]);
#pragma unroll
                for (int j = 0; j < 8; j++) {
                    uint32_t b[2];
                    const float* kp = Kcur + (j * 8 + g) * LDK + k8 + t;
                    b[0] = fbits(kp[0]);
                    b[1] = fbits(kp[4]);
                    mma_tf32(s[j], a, b);
                }
            }

            // scale + (rare) causal mask
            if (kb + 63 > q0 + HIST) {
#pragma unroll
                for (int j = 0; j < 8; j++) {
                    int colg = kb + j * 8 + 2 * t;
                    s[j][0] = (colg     <= row0g + HIST)     ? s[j][0] * SC : -1e30f;
                    s[j][1] = (colg + 1 <= row0g + HIST)     ? s[j][1] * SC : -1e30f;
                    s[j][2] = (colg     <= row0g + 8 + HIST) ? s[j][2] * SC : -1e30f;
                    s[j][3] = (colg + 1 <= row0g + 8 + HIST) ? s[j][3] * SC : -1e30f;
                }
            } else {
#pragma unroll
                for (int j = 0; j < 8; j++) {
                    s[j][0] *= SC; s[j][1] *= SC;
                    s[j][2] *= SC; s[j][3] *= SC;
                }
            }

            // online softmax (quad reduce)
            float mx0 = -1e30f, mx1 = -1e30f;
#pragma unroll
            for (int j = 0; j < 8; j++) {
                mx0 = fmaxf(mx0, fmaxf(s[j][0], s[j][1]));
                mx1 = fmaxf(mx1, fmaxf(s[j][2], s[j][3]));
            }
            mx0 = fmaxf(mx0, __shfl_xor_sync(0xffffffffu, mx0, 1));
            mx0 = fmaxf(mx0, __shfl_xor_sync(0xffffffffu, mx0, 2));
            mx1 = fmaxf(mx1, __shfl_xor_sync(0xffffffffu, mx1, 1));
            mx1 = fmaxf(mx1, __shfl_xor_sync(0xffffffffu, mx1, 2));
            float mn0 = fmaxf(m0, mx0), mn1 = fmaxf(m1, mx1);
            float c0 = exp2f(m0 - mn0), c1 = exp2f(m1 - mn1);
            m0 = mn0; m1 = mn1;
            float sum0 = 0.f, sum1 = 0.f;
#pragma unroll
            for (int j = 0; j < 8; j++) {
                s[j][0] = exp2f(s[j][0] - m0);
                s[j][1] = exp2f(s[j][1] - m0);
                s[j][2] = exp2f(s[j][2] - m1);
                s[j][3] = exp2f(s[j][3] - m1);
                sum0 += s[j][0] + s[j][1];
                sum1 += s[j][2] + s[j][3];
            }
            sum0 += __shfl_xor_sync(0xffffffffu, sum0, 1);
            sum0 += __shfl_xor_sync(0xffffffffu, sum0, 2);
            sum1 += __shfl_xor_sync(0xffffffffu, sum1, 1);
            sum1 += __shfl_xor_sync(0xffffffffu, sum1, 2);
            l0 = l0 * c0 + sum0;
            l1 = l1 * c1 + sum1;

#pragma unroll
            for (int j = 0; j < 16; j++) {
                o[j][0] *= c0; o[j][1] *= c0;
                o[j][2] *= c1; o[j][3] *= c1;
            }

            // stage P (tf32) in warp-private slab
            {
                float* p0 = Ps + (w * 16 + g) * LDP;
                float* p1 = p0 + 8 * LDP;
#pragma unroll
                for (int j = 0; j < 8; j++) {
                    *(float2*)(p0 + j * 8 + 2 * t) =
                        make_float2(tf32r(s[j][0]), tf32r(s[j][1]));
                    *(float2*)(p1 + j * 8 + 2 * t) =
                        make_float2(tf32r(s[j][2]), tf32r(s[j][3]));
                }
            }
            __syncwarp();

            if (more) { CP_WAIT(1); } else { CP_WAIT(0); }   // V(kt) done
            __syncthreads();

            // O += P @ V
#pragma unroll
            for (int k8 = 0; k8 < 64; k8 += 8) {
                uint32_t a[4];
                const float* pb = Ps + (w * 16 + g) * LDP + k8 + t;
                a[0] = fbits(pb[0]);
                a[1] = fbits(pb[8 * LDP]);
                a[2] = fbits(pb[4]);
                a[3] = fbits(pb[8 * LDP + 4]);
#pragma unroll
                for (int j = 0; j < 16; j++) {
                    uint32_t b[2];
                    const float* vb = Vs + (k8 + t) * LDV + j * 8 + g;
                    b[0] = fbits(vb[0]);
                    b[1] = fbits(vb[4 * LDV]);
                    mma_tf32(o[j], a, b);
                }
            }
            __syncthreads();
        }

        // normalize + store (tf32-rounded: feeds Wo GEMM via cp.async)
        float inv0 = 1.f / l0, inv1 = 1.f / l1;
#pragma unroll
        for (int j = 0; j < 16; j++) {
            float* a0 = g_att + (size_t)row0g * HID + head * DH + j * 8 + 2 * t;
            float* a1 = a0 + 8 * HID;
            *(float2*)a0 = make_float2(tf32r(o[j][0] * inv0),
                                       tf32r(o[j][1] * inv0));
            *(float2*)a1 = make_float2(tf32r(o[j][2] * inv1),
                                       tf32r(o[j][3] * inv1));
        }
        __syncthreads();
    }
}

// ---------------------------------------------------------------------------
extern "C" void kernel_launch(void* const* d_in, const int* in_sizes, int n_in,
                              void* d_out, int out_size)
{
    const float* x      = (const float*)d_in[0];
    const float* Wq     = (const float*)d_in[1];
    const float* bq     = (const float*)d_in[2];
    const float* Wk     = (const float*)d_in[3];
    const float* bk     = (const float*)d_in[4];
    const float* Wv     = (const float*)d_in[5];
    const float* bv     = (const float*)d_in[6];
    const float* Wo     = (const float*)d_in[7];
    const float* k_hist = (const float*)d_in[8];
    const float* v_hist = (const float*)d_in[9];
    const float* fcos   = (const float*)d_in[10];
    const float* fsin   = (const float*)d_in[11];
    float* out = (float*)d_out;

    cudaFuncSetAttribute(attn_kernel,
                         cudaFuncAttributeMaxDynamicSharedMemorySize, ATTN_SMEM);
    cudaFuncSetAttribute(gemm_qkv_kernel,
                         cudaFuncAttributeMaxDynamicSharedMemorySize, GEMM_SMEM);
    cudaFuncSetAttribute(gemm_wo_kernel,
                         cudaFuncAttributeMaxDynamicSharedMemorySize, GEMM_SMEM);

    // pre-round inputs to tf32, fill K/V history, reset work queue
    cvt_kernel<<<2368, 256>>>((const float4*)x, (const float4*)Wq,
                              (const float4*)Wk, (const float4*)Wv,
                              (const float4*)Wo, (const float4*)k_hist,
                              (const float4*)v_hist);

    // fused QKV projection
    gemm_qkv_kernel<<<dim3(16, 16), 256, GEMM_SMEM>>>(bq, bk, bv);

    // RoPE
    rope_kernel<<<Q_LEN * 14, 64>>>(fcos, fsin);

    // attention (persistent, work-queue balanced)
    attn_kernel<<<148, 256, ATTN_SMEM>>>();

    // output projection
    gemm_wo_kernel<<<dim3(HID / 128, Q_LEN / 128), 256, GEMM_SMEM>>>(out);
}